// round 11
// baseline (speedup 1.0000x reference)
#include <cuda_runtime.h>
#include <cuda_bf16.h>
#include <cstdint>

#define B_TOT   4096
#define N_IN    512
#define N_TOT   2048
#define N_EVAL  1536
#define N_OUTC  256
#define NPH     24
#define MROWS   64
#define NCTA    64
#define NTHREADS 320      // warps 0-7 compute, warps 8-9 serial
#define DENSE_T 256

// Pre-baked bf16 hi/lo tiles, stride-72 rows (144 B): conflict-free LDSM.
// A tile: hi[64*72] + lo[64*72] = 18432 B ; B tile: hi[64*72]+lo[64*72] = 18432 B
__device__ __align__(256) char g_AT[64u * 32u * 18432u];    // ~37.7 MB
__device__ __align__(256) char g_BT[24u * 32u * 18432u];    // ~14 MB

#define AT_TILE(rb, c) (g_AT + (size_t)((rb) * 32 + (c)) * 18432u)
#define BT_TILE(q, c)  (g_BT + (size_t)((q) * 32 + (c)) * 18432u)

// ---- shared memory layout (bytes) ----
#define SM_A    0                 // 4 x 18432  A ring
#define SM_B    73728             // 4 x 18432  B ring
#define SM_DEPA 147456            // 18432  dep A (serial warps write ONLY)
#define SM_DEPB 165888            // 18432  dep B
#define SM_SWB  184320            // 16384  in-block weights f32 [64][64]
#define SM_SB   200704            // 256    biases
#define SM_SZ   200960            // 64*65*4 Z tile
#define SMEM_BYTES 217600

#define BAR_ALL()   asm volatile("bar.sync 1, 320;" ::: "memory")
#define BAR_DENSE() asm volatile("bar.sync 2, 256;" ::: "memory")
#define CP_COMMIT() asm volatile("cp.async.commit_group;" ::: "memory")
#define CP_WAIT0()  asm volatile("cp.async.wait_group 0;" ::: "memory")
#define CP_WAIT2()  asm volatile("cp.async.wait_group 2;" ::: "memory")

__device__ __forceinline__ uint32_t smem_u32(const void* p) {
    uint32_t a;
    asm("{ .reg .u64 t; cvta.to.shared.u64 t, %1; cvt.u32.u64 %0, t; }"
        : "=r"(a) : "l"(p));
    return a;
}
__device__ __forceinline__ void cp16(uint32_t d, const void* s) {
    asm volatile("cp.async.cg.shared.global [%0], [%1], 16;"
                 :: "r"(d), "l"(s) : "memory");
}
__device__ __forceinline__ void ldsm4(uint32_t* r, uint32_t addr) {
    asm volatile("ldmatrix.sync.aligned.m8n8.x4.shared.b16 {%0,%1,%2,%3}, [%4];"
                 : "=r"(r[0]), "=r"(r[1]), "=r"(r[2]), "=r"(r[3]) : "r"(addr));
}
__device__ __forceinline__ void hmma(float* d, const uint32_t* a, const uint32_t* b) {
    asm volatile("mma.sync.aligned.m16n8k16.row.col.f32.bf16.bf16.f32 "
                 "{%0,%1,%2,%3}, {%4,%5,%6,%7}, {%8,%9}, {%0,%1,%2,%3};"
                 : "+f"(d[0]), "+f"(d[1]), "+f"(d[2]), "+f"(d[3])
                 : "r"(a[0]), "r"(a[1]), "r"(a[2]), "r"(a[3]),
                   "r"(b[0]), "r"(b[1]));
}
__device__ __forceinline__ uint32_t pack2(__nv_bfloat16 a, __nv_bfloat16 b) {
    return (uint32_t)__bfloat16_as_ushort(a) |
           ((uint32_t)__bfloat16_as_ushort(b) << 16);
}
__device__ __forceinline__ void split_pack(float v0, float v1,
                                           uint32_t& hp, uint32_t& lp) {
    __nv_bfloat16 h0 = __float2bfloat16(v0), h1 = __float2bfloat16(v1);
    __nv_bfloat16 l0 = __float2bfloat16(v0 - __bfloat162float(h0));
    __nv_bfloat16 l1 = __float2bfloat16(v1 - __bfloat162float(h1));
    hp = pack2(h0, h1); lp = pack2(l0, l1);
}
__device__ __forceinline__ float sigmoid5(float z) {
    float t5 = fminf(fmaxf(5.0f * z, -60.0f), 60.0f);
    float e;
    asm("ex2.approx.f32 %0, %1;" : "=f"(e) : "f"(t5 * (-1.4426950408889634f)));
    float sig;
    asm("rcp.approx.f32 %0, %1;" : "=f"(sig) : "f"(1.0f + e));
    return sig;
}

// ---- prep: bake pre-packed hi/lo bf16 tiles ----
__global__ void __launch_bounds__(256) prep_X(const float* __restrict__ x) {
    const int rb = blockIdx.x, c = blockIdx.y;   // 64 x 8
    char* baseH = AT_TILE(rb, c);
    char* baseL = baseH + 9216;
    for (int i = threadIdx.x; i < 64 * 32; i += 256) {
        int r = i >> 5, kp = i & 31;
        const float* src = x + (size_t)(rb * 64 + r) * N_IN + c * 64 + kp * 2;
        uint32_t hp, lp; split_pack(src[0], src[1], hp, lp);
        uint32_t off = (uint32_t)(r * 144 + kp * 4);
        *(uint32_t*)(baseH + off) = hp;
        *(uint32_t*)(baseL + off) = lp;
    }
}
__global__ void __launch_bounds__(256) prep_W(const float* __restrict__ W) {
    const int q = blockIdx.x, c = blockIdx.y;    // 24 x 32
    if (c > 7 + q) return;
    char* baseH = BT_TILE(q, c);
    char* baseL = baseH + 9216;
    for (int i = threadIdx.x; i < 64 * 32; i += 256) {
        int n = i >> 5, kp = i & 31;
        const float* src = W + (size_t)(q * 64 + n) * N_TOT + c * 64 + kp * 2;
        uint32_t hp, lp; split_pack(src[0], src[1], hp, lp);
        uint32_t off = (uint32_t)(n * 144 + kp * 4);
        *(uint32_t*)(baseH + off) = hp;
        *(uint32_t*)(baseL + off) = lp;
    }
}

extern __shared__ __align__(16) char smem[];

__global__ void __launch_bounds__(NTHREADS, 1)
ff_kernel(const float* __restrict__ W, const float* __restrict__ bias,
          float* __restrict__ out) {
    const int t = threadIdx.x;
    const int wid = t >> 5, lane = t & 31;
    const int rb = blockIdx.x;
    const uint32_t sb32 = smem_u32(smem);
    float* sZ  = (float*)(smem + SM_SZ);
    float* sWb = (float*)(smem + SM_SWB);
    float* sB  = (float*)(smem + SM_SB);

    if (wid < 8) {
        // ============ COMPUTE WARPS: 16x32 tile each (64x64 total) ============
        const int row0 = (wid & 3) * 16;
        const int col0 = (wid >> 2) * 32;
        const int g = lane >> 3, li = lane & 7;
        // ldmatrix addressing (verified on HW in R9): A frag order
        // (r,k)/(r+8,k)/(r,k+8)/(r+8,k+8); B frag order (n,k)/(n,k+8)/(n+8,..)
        const uint32_t offA  = (uint32_t)((row0 + li + (g & 1) * 8) * 144 + (g >> 1) * 16);
        const uint32_t offB  = (uint32_t)((col0 + li + (g >> 1) * 8) * 144 + (g & 1) * 16);
        const uint32_t offB2 = offB + 16u * 144u;
        float acc[16] = {};

        auto pf_A = [&](uint32_t doff, const char* src) {
            for (int i = t; i < 1152; i += DENSE_T) cp16(sb32 + doff + i * 16, src + i * 16);
        };
        auto pf_B = [&](uint32_t doff, const char* src) {
            for (int i = t; i < 1152; i += DENSE_T) cp16(sb32 + doff + i * 16, src + i * 16);
        };
        auto mac_chunk = [&](uint32_t aBase, uint32_t bBase) {
            #pragma unroll
            for (int kk = 0; kk < 4; ++kk) {
                uint32_t ah[4], al[4], bh0[4], bh1[4], bl0[4], bl1[4];
                ldsm4(ah,  aBase + offA + kk * 32);
                ldsm4(al,  aBase + 9216u + offA + kk * 32);
                ldsm4(bh0, bBase + offB + kk * 32);
                ldsm4(bh1, bBase + offB2 + kk * 32);
                ldsm4(bl0, bBase + 9216u + offB + kk * 32);
                ldsm4(bl1, bBase + 9216u + offB2 + kk * 32);
                hmma(acc + 0,  ah, bh0); hmma(acc + 4,  ah, bh0 + 2);
                hmma(acc + 8,  ah, bh1); hmma(acc + 12, ah, bh1 + 2);
                hmma(acc + 0,  ah, bl0); hmma(acc + 4,  ah, bl0 + 2);
                hmma(acc + 8,  ah, bl1); hmma(acc + 12, ah, bl1 + 2);
                hmma(acc + 0,  al, bh0); hmma(acc + 4,  al, bh0 + 2);
                hmma(acc + 8,  al, bh1); hmma(acc + 12, al, bh1 + 2);
            }
        };
        auto chunk_loop = [&](int q, int nch, bool doDep) {
            pf_A(SM_A, AT_TILE(rb, 0));               pf_B(SM_B, BT_TILE(q, 0));
            CP_COMMIT();
            pf_A(SM_A + 18432u, AT_TILE(rb, 1));      pf_B(SM_B + 18432u, BT_TILE(q, 1));
            CP_COMMIT();
            for (int c = 0; c < nch; ++c) {
                if (c + 2 < nch) {
                    uint32_t s = (uint32_t)((c + 2) & 3);
                    pf_A(SM_A + s * 18432u, AT_TILE(rb, c + 2));
                    pf_B(SM_B + s * 18432u, BT_TILE(q, c + 2));
                } else if (doDep && c + 2 == nch) {
                    pf_B(SM_DEPB, BT_TILE(q, 7 + q));   // dep WEIGHTS only
                }
                CP_COMMIT();            // exactly one group per iter (may be empty)
                CP_WAIT2();             // group for chunk c complete
                BAR_DENSE();            // publish cp data + protect ring reuse
                mac_chunk(sb32 + SM_A + (uint32_t)(c & 3) * 18432u,
                          sb32 + SM_B + (uint32_t)(c & 3) * 18432u);
            }
        };

        // ---- prologue: phase 0 (8 chunks, all from x) ----
        chunk_loop(0, 8, false);

        for (int p = 0; p < NPH; ++p) {
            const int e0 = p * 64, S = N_IN + e0;

            // segment A: stage sWb/sB, dep mma, Z write
            for (int i = t; i < 1024; i += DENSE_T) {
                int n = i >> 4, j = i & 15;
                cp16(sb32 + SM_SWB + (uint32_t)i * 16,
                     W + (size_t)(e0 + n) * N_TOT + S + j * 4);
            }
            if (t < 16) cp16(sb32 + SM_SB + (uint32_t)t * 16, bias + e0 + t * 4);
            CP_COMMIT();
            CP_WAIT0();                 // sWb + sB + dep-B drained
            BAR_DENSE();                // + all warps done reading A/B ring
            if (p > 0) mac_chunk(sb32 + SM_DEPA, sb32 + SM_DEPB);
            {
                int m = row0 + (lane >> 2), n = col0 + (lane & 3) * 2;
                float* z = sZ + m * 65 + n;
                #pragma unroll
                for (int nt = 0; nt < 4; ++nt) {
                    z[nt * 8]          = acc[nt * 4 + 0];
                    z[nt * 8 + 1]      = acc[nt * 4 + 1];
                    z[8 * 65 + nt * 8]     = acc[nt * 4 + 2];
                    z[8 * 65 + nt * 8 + 1] = acc[nt * 4 + 3];
                    acc[nt*4+0] = acc[nt*4+1] = acc[nt*4+2] = acc[nt*4+3] = 0.f;
                }
            }
            BAR_ALL();     // serial warps may start (Z, sWb, sB ready)

            if (p < NPH - 1)
                chunk_loop(p + 1, 8 + p, true);
            BAR_ALL();     // phase end (serial done; SM_DEPA ready)
        }
    } else {
        // ============ SERIAL WARPS 8-9 (lane = batch row) ============
        const int r = (wid - 8) * 32 + lane;
        for (int p = 0; p < NPH; ++p) {
            const int e0 = p * 64;
            BAR_ALL();     // Z + sWb + sB ready

            float o[64];
            const float* zrow = sZ + r * 65;
            #pragma unroll
            for (int k = 0; k < 64; ++k) {
                float z  = zrow[k] + sB[k];
                float z1 = 0.0f;
                const float* wk = sWb + k * 64;
                #pragma unroll
                for (int j = 0; j + 1 < k; j += 2) {
                    z  = fmaf(o[j],     wk[j],     z);
                    z1 = fmaf(o[j + 1], wk[j + 1], z1);
                }
                if (k & 1) z = fmaf(o[k - 1], wk[k - 1], z);
                o[k] = sigmoid5(z + z1);
            }

            if (p < NPH - 1) {
                // dep A (smem, sole source next phase) + global tile (phases >= p+2)
                char* sH = smem + SM_DEPA;
                char* gH = AT_TILE(rb, 8 + p);
                #pragma unroll
                for (int kp = 0; kp < 32; ++kp) {
                    uint32_t hp, lp;
                    split_pack(o[2 * kp], o[2 * kp + 1], hp, lp);
                    uint32_t off = (uint32_t)(r * 144 + kp * 4);
                    *(uint32_t*)(sH + off) = hp;
                    *(uint32_t*)(sH + off + 9216) = lp;
                    *(uint32_t*)(gH + off) = hp;
                    *(uint32_t*)(gH + off + 9216) = lp;
                }
            }
            if (p >= 20) {
                float* orow = out + (size_t)(rb * 64 + r) * N_OUTC + (e0 - 1280);
                #pragma unroll
                for (int k = 0; k < 64; ++k) orow[k] = o[k];
            }
            __threadfence();   // g_AT writes visible to later cp.async (L2 path)
            BAR_ALL();         // phase end
        }
    }
}

extern "C" void kernel_launch(void* const* d_in, const int* in_sizes, int n_in,
                              void* d_out, int out_size) {
    const float* x = (const float*)d_in[0];   // [4096, 512]
    const float* W = (const float*)d_in[1];   // [1536, 2048]
    const float* b = (const float*)d_in[2];   // [1536]
    float* out = (float*)d_out;               // [4096, 256]
    (void)in_sizes; (void)n_in; (void)out_size;

    prep_X<<<dim3(64, 8), 256>>>(x);
    prep_W<<<dim3(24, 32), 256>>>(W);

    cudaFuncSetAttribute(ff_kernel, cudaFuncAttributeMaxDynamicSharedMemorySize,
                         SMEM_BYTES);
    ff_kernel<<<NCTA, NTHREADS, SMEM_BYTES>>>(W, b, out);
}

// round 12
// speedup vs baseline: 1.7280x; 1.7280x over previous
#include <cuda_runtime.h>
#include <cuda_fp16.h>
#include <cstdint>

#define B_TOT   4096
#define N_IN    512
#define N_TOT   2048
#define N_EVAL  1536
#define N_OUTC  256
#define NPH     24
#define MROWS   32
#define NCTA    128
#define NTHREADS 160      // warps 0-3 compute, warp 4 serial
#define DENSE_T 128

// Pre-baked tiles, stride-72 rows (144 B): conflict-free scalar LDS.
// A tile (fp16 single): 32 rows x 144 B = 4608 B
// B tile (fp16 hi + fp16 scaled-lo): 2 x 64 x 144 = 18432 B
__device__ __align__(256) char g_AT[128u * 32u * 4608u];    // ~18.9 MB
__device__ __align__(256) char g_BT[24u * 32u * 18432u];    // ~14 MB

#define AT_TILE(rb, c) (g_AT + (size_t)((rb) * 32 + (c)) * 4608u)
#define BT_TILE(q, c)  (g_BT + (size_t)((q) * 32 + (c)) * 18432u)

// ---- shared memory layout (bytes) ----
#define SM_A    0                 // 4 x 4608   A ring
#define SM_B    18432             // 4 x 18432  B ring
#define SM_DEPA 92160             // 4608   dep A (serial warp writes ONLY)
#define SM_DEPB 96768             // 18432  dep B
#define SM_SWB  115200            // 16384  in-block weights f32 [64][64]
#define SM_SB   131584            // 256    biases
#define SM_SZ   131840            // 32*65*4 Z tile
#define SMEM_BYTES 140160

#define INV4096 (1.0f / 4096.0f)

#define BAR_ALL()   asm volatile("bar.sync 1, 160;" ::: "memory")
#define BAR_DENSE() asm volatile("bar.sync 2, 128;" ::: "memory")
#define CP_COMMIT() asm volatile("cp.async.commit_group;" ::: "memory")
#define CP_WAIT0()  asm volatile("cp.async.wait_group 0;" ::: "memory")
#define CP_WAIT2()  asm volatile("cp.async.wait_group 2;" ::: "memory")

__device__ __forceinline__ uint32_t smem_u32(const void* p) {
    uint32_t a;
    asm("{ .reg .u64 t; cvta.to.shared.u64 t, %1; cvt.u32.u64 %0, t; }"
        : "=r"(a) : "l"(p));
    return a;
}
__device__ __forceinline__ void cp16(uint32_t d, const void* s) {
    asm volatile("cp.async.cg.shared.global [%0], [%1], 16;"
                 :: "r"(d), "l"(s) : "memory");
}
__device__ __forceinline__ void hmma(float* d, const uint32_t* a, const uint32_t* b) {
    asm volatile("mma.sync.aligned.m16n8k16.row.col.f32.f16.f16.f32 "
                 "{%0,%1,%2,%3}, {%4,%5,%6,%7}, {%8,%9}, {%0,%1,%2,%3};"
                 : "+f"(d[0]), "+f"(d[1]), "+f"(d[2]), "+f"(d[3])
                 : "r"(a[0]), "r"(a[1]), "r"(a[2]), "r"(a[3]),
                   "r"(b[0]), "r"(b[1]));
}
__device__ __forceinline__ uint32_t packh2(float v0, float v1) {
    __half h0 = __float2half(v0), h1 = __float2half(v1);
    return (uint32_t)__half_as_ushort(h0) | ((uint32_t)__half_as_ushort(h1) << 16);
}
// W split: hi = fp16(W); lo = fp16((W - hi) * 4096)  -> W ~= hi + lo/4096
__device__ __forceinline__ void splitw(float v0, float v1, uint32_t& hp, uint32_t& lp) {
    __half h0 = __float2half(v0), h1 = __float2half(v1);
    float r0 = (v0 - __half2float(h0)) * 4096.0f;
    float r1 = (v1 - __half2float(h1)) * 4096.0f;
    hp = (uint32_t)__half_as_ushort(h0) | ((uint32_t)__half_as_ushort(h1) << 16);
    lp = packh2(r0, r1);
}
__device__ __forceinline__ float sigmoid5(float z) {
    float t5 = fminf(fmaxf(5.0f * z, -60.0f), 60.0f);
    float e;
    asm("ex2.approx.f32 %0, %1;" : "=f"(e) : "f"(t5 * (-1.4426950408889634f)));
    float sig;
    asm("rcp.approx.f32 %0, %1;" : "=f"(sig) : "f"(1.0f + e));
    return sig;
}

// ---- prep: bake fp16 tiles ----
__global__ void __launch_bounds__(256) prep_X(const float* __restrict__ x) {
    const int rb = blockIdx.x, c = blockIdx.y;   // 128 x 8
    char* base = AT_TILE(rb, c);
    for (int i = threadIdx.x; i < 32 * 32; i += 256) {
        int r = i >> 5, kp = i & 31;
        const float* src = x + (size_t)(rb * 32 + r) * N_IN + c * 64 + kp * 2;
        *(uint32_t*)(base + (uint32_t)(r * 144 + kp * 4)) = packh2(src[0], src[1]);
    }
}
__global__ void __launch_bounds__(256) prep_W(const float* __restrict__ W) {
    const int q = blockIdx.x, c = blockIdx.y;    // 24 x 32
    if (c > 7 + q) return;
    char* baseH = BT_TILE(q, c);
    char* baseL = baseH + 9216;
    for (int i = threadIdx.x; i < 64 * 32; i += 256) {
        int n = i >> 5, kp = i & 31;
        const float* src = W + (size_t)(q * 64 + n) * N_TOT + c * 64 + kp * 2;
        uint32_t hp, lp; splitw(src[0], src[1], hp, lp);
        uint32_t off = (uint32_t)(n * 144 + kp * 4);
        *(uint32_t*)(baseH + off) = hp;
        *(uint32_t*)(baseL + off) = lp;
    }
}

extern __shared__ __align__(16) char smem[];

__global__ void __launch_bounds__(NTHREADS, 1)
ff_kernel(const float* __restrict__ W, const float* __restrict__ bias,
          float* __restrict__ out) {
    const int t = threadIdx.x;
    const int wid = t >> 5, lane = t & 31;
    const int rb = blockIdx.x;
    const uint32_t sb32 = smem_u32(smem);
    float* sZ  = (float*)(smem + SM_SZ);
    float* sWb = (float*)(smem + SM_SWB);
    float* sB  = (float*)(smem + SM_SB);

    if (wid < 4) {
        // ============ COMPUTE WARPS: 16x32 tile each (2x2 layout) ============
        const int row0 = (wid & 1) * 16;
        const int col0 = (wid >> 1) * 32;
        float accM[4][4] = {};        // a * w_hi
        float accL[4][4] = {};        // a * w_lo*4096  (combined at Z-write)

        auto pf_A = [&](uint32_t doff, const char* src) {
            for (int i = t; i < 288; i += DENSE_T) cp16(sb32 + doff + i * 16, src + i * 16);
        };
        auto pf_B = [&](uint32_t doff, const char* src) {
            for (int i = t; i < 1152; i += DENSE_T) cp16(sb32 + doff + i * 16, src + i * 16);
        };
        auto mac_chunk = [&](const char* A, const char* Bt) {
            #pragma unroll
            for (int kk = 0; kk < 4; ++kk) {
                const char* pa = A + (row0 + (lane >> 2)) * 144 + (lane & 3) * 4 + kk * 32;
                uint32_t ah[4] = { *(const uint32_t*)(pa),
                                   *(const uint32_t*)(pa + 1152),
                                   *(const uint32_t*)(pa + 16),
                                   *(const uint32_t*)(pa + 1168) };
                #pragma unroll
                for (int nt = 0; nt < 4; ++nt) {
                    const char* pb = Bt + (col0 + nt * 8 + (lane >> 2)) * 144
                                     + (lane & 3) * 4 + kk * 32;
                    uint32_t bh[2] = { *(const uint32_t*)(pb),
                                       *(const uint32_t*)(pb + 16) };
                    uint32_t bl[2] = { *(const uint32_t*)(pb + 9216),
                                       *(const uint32_t*)(pb + 9232) };
                    hmma(accM[nt], ah, bh);
                    hmma(accL[nt], ah, bl);
                }
            }
        };
        auto chunk_loop = [&](int q, int nch, bool doDep) {
            pf_A(SM_A, AT_TILE(rb, 0));              pf_B(SM_B, BT_TILE(q, 0));
            CP_COMMIT();
            pf_A(SM_A + 4608u, AT_TILE(rb, 1));      pf_B(SM_B + 18432u, BT_TILE(q, 1));
            CP_COMMIT();
            for (int c = 0; c < nch; ++c) {
                if (c + 2 < nch) {
                    uint32_t s = (uint32_t)((c + 2) & 3);
                    pf_A(SM_A + s * 4608u,  AT_TILE(rb, c + 2));
                    pf_B(SM_B + s * 18432u, BT_TILE(q, c + 2));
                } else if (doDep && c + 2 == nch) {
                    pf_B(SM_DEPB, BT_TILE(q, 7 + q));   // dep WEIGHTS only
                }
                CP_COMMIT();            // exactly one group per iter (may be empty)
                CP_WAIT2();             // group for chunk c complete
                BAR_DENSE();            // publish cp data + protect ring reuse
                mac_chunk(smem + SM_A + (size_t)(c & 3) * 4608u,
                          smem + SM_B + (size_t)(c & 3) * 18432u);
            }
        };

        // ---- prologue: phase 0 (8 chunks, all from x) ----
        chunk_loop(0, 8, false);

        for (int p = 0; p < NPH; ++p) {
            const int e0 = p * 64, S = N_IN + e0;

            // segment A: stage sWb/sB, dep mma, Z write
            for (int i = t; i < 1024; i += DENSE_T) {
                int n = i >> 4, j = i & 15;
                cp16(sb32 + SM_SWB + (uint32_t)i * 16,
                     W + (size_t)(e0 + n) * N_TOT + S + j * 4);
            }
            if (t < 16) cp16(sb32 + SM_SB + (uint32_t)t * 16, bias + e0 + t * 4);
            CP_COMMIT();
            CP_WAIT0();                 // sWb + sB + dep-B drained
            BAR_DENSE();                // + all warps done reading A/B ring
            if (p > 0) mac_chunk(smem + SM_DEPA, smem + SM_DEPB);
            {
                int m = row0 + (lane >> 2), cb = (lane & 3) * 2;
                #pragma unroll
                for (int nt = 0; nt < 4; ++nt) {
                    float* z = sZ + m * 65 + col0 + nt * 8 + cb;
                    z[0]          = accM[nt][0] + accL[nt][0] * INV4096;
                    z[1]          = accM[nt][1] + accL[nt][1] * INV4096;
                    z[8 * 65]     = accM[nt][2] + accL[nt][2] * INV4096;
                    z[8 * 65 + 1] = accM[nt][3] + accL[nt][3] * INV4096;
                    accM[nt][0] = accM[nt][1] = accM[nt][2] = accM[nt][3] = 0.f;
                    accL[nt][0] = accL[nt][1] = accL[nt][2] = accL[nt][3] = 0.f;
                }
            }
            BAR_ALL();     // serial warp may start (Z, sWb, sB ready)

            if (p < NPH - 1)
                chunk_loop(p + 1, 8 + p, true);
            BAR_ALL();     // phase end (serial done; SM_DEPA ready)
        }
    } else {
        // =================== SERIAL WARP (lane = row) ===================
        const int r = lane;
        for (int p = 0; p < NPH; ++p) {
            const int e0 = p * 64;
            BAR_ALL();     // Z + sWb + sB ready

            float o[64];
            const float* zrow = sZ + r * 65;
            #pragma unroll
            for (int k = 0; k < 64; ++k) {
                float z  = zrow[k] + sB[k];
                float z1 = 0.0f;
                const float* wk = sWb + k * 64;
                #pragma unroll
                for (int j = 0; j + 1 < k; j += 2) {
                    z  = fmaf(o[j],     wk[j],     z);
                    z1 = fmaf(o[j + 1], wk[j + 1], z1);
                }
                if (k & 1) z = fmaf(o[k - 1], wk[k - 1], z);
                o[k] = sigmoid5(z + z1);
            }

            if (p < NPH - 1) {
                // dep A (smem, sole source next phase) + global tile (phases >= p+2)
                char* sH = smem + SM_DEPA;
                char* gH = AT_TILE(rb, 8 + p);
                #pragma unroll
                for (int kp = 0; kp < 32; ++kp) {
                    uint32_t hp = packh2(o[2 * kp], o[2 * kp + 1]);
                    uint32_t off = (uint32_t)(r * 144 + kp * 4);
                    *(uint32_t*)(sH + off) = hp;
                    *(uint32_t*)(gH + off) = hp;
                }
            }
            if (p >= 20) {
                float* orow = out + (size_t)(rb * 32 + r) * N_OUTC + (e0 - 1280);
                #pragma unroll
                for (int k = 0; k < 64; ++k) orow[k] = o[k];
            }
            __threadfence();   // g_AT writes visible to later cp.async (L2 path)
            BAR_ALL();         // phase end
        }
    }
}

extern "C" void kernel_launch(void* const* d_in, const int* in_sizes, int n_in,
                              void* d_out, int out_size) {
    const float* x = (const float*)d_in[0];   // [4096, 512]
    const float* W = (const float*)d_in[1];   // [1536, 2048]
    const float* b = (const float*)d_in[2];   // [1536]
    float* out = (float*)d_out;               // [4096, 256]
    (void)in_sizes; (void)n_in; (void)out_size;

    prep_X<<<dim3(128, 8), 256>>>(x);
    prep_W<<<dim3(24, 32), 256>>>(W);

    cudaFuncSetAttribute(ff_kernel, cudaFuncAttributeMaxDynamicSharedMemorySize,
                         SMEM_BYTES);
    ff_kernel<<<NCTA, NTHREADS, SMEM_BYTES>>>(W, b, out);
}